// round 16
// baseline (speedup 1.0000x reference)
#include <cuda_runtime.h>
#include <math.h>

#define B_   32
#define EMB_ 640
#define SCALE_ 0.17677669529663688f  // 1/sqrt(32)

typedef unsigned long long ull;

// ---------------- packed f32x2 helpers ----------------
__device__ __forceinline__ ull dup2(float x) {
    ull r; asm("mov.b64 %0, {%1, %1};" : "=l"(r) : "f"(x)); return r;
}
__device__ __forceinline__ void fma2(ull& d, ull a, ull b) {
    asm("fma.rn.f32x2 %0, %1, %2, %0;" : "+l"(d) : "l"(a), "l"(b));
}
__device__ __forceinline__ void unpk(ull v, float& lo, float& hi) {
    asm("mov.b64 {%0, %1}, %2;" : "=f"(lo), "=f"(hi) : "l"(v));
}

// ---------------- scratch ----------------
__device__ float g_h  [32*64*64*192];   // BHWC after GN1+adafm
__device__ float g_xa [32*192*64*64];   // BCHW after attention residual
__device__ float g_h2 [32*64*64*192];   // BHWC after GN2+adafm
__device__ float g_kc1[32*4096];
__device__ float g_kc2[32*4096];
__device__ float g_st1[32*32*2];
__device__ float g_st2[32*32*2];
__device__ float g_qkvT[6*192*96];      // [head][k][j]
__device__ float g_pT  [192*192];       // [k][co]
__device__ float g_f1T [192*768];       // [k][j]
__device__ float g_f2T [768*192];       // [j][co]

__constant__ float c_c8[8] = {1.f, 0.70710678118654752f, 0.f, -0.70710678118654752f,
                              -1.f, -0.70710678118654752f, 0.f, 0.70710678118654752f};

// ---------------- weight transposition ----------------
__global__ __launch_bounds__(256) void k_prep(
    const float* __restrict__ qkv_w, const float* __restrict__ proj_w,
    const float* __restrict__ fc1_w, const float* __restrict__ fc2_w)
{
    int idx = blockIdx.x * 256 + threadIdx.x;
    if (idx < 110592) {
        int h = idx / 18432, r = idx % 18432;
        int i = r / 96, j = r % 96;
        int kind = j >> 5, d = j & 31;
        g_qkvT[idx] = qkv_w[(kind*192 + h*32 + d)*192 + i];
    } else if (idx < 147456) {
        int r = idx - 110592;
        int i = r / 192, co = r % 192;
        g_pT[r] = proj_w[co*192 + i];
    } else if (idx < 294912) {
        int r = idx - 147456;
        int i = r / 768, j = r % 768;
        g_f1T[r] = fc1_w[j*192 + i];
    } else if (idx < 442368) {
        int r = idx - 294912;
        int j = r / 192, co = r % 192;
        g_f2T[r] = fc2_w[co*768 + j];
    }
}

// ---------------- K0 ----------------
__global__ __launch_bounds__(128) void k0_ada(
    const float* __restrict__ t,
    const float* __restrict__ wm, const float* __restrict__ bm,
    const float* __restrict__ wl, const float* __restrict__ bl)
{
    int b = blockIdx.x, tid = threadIdx.x;
    __shared__ float st[EMB_];
    __shared__ float sv[80];
    __shared__ float kk[2][64];
    for (int i = tid; i < EMB_; i += 128) {
        float v = t[b*EMB_ + i];
        st[i] = v / (1.f + expf(-v));
    }
    __syncthreads();
    if (tid < 80) {
        int j = tid % 40;
        const float* w = (tid < 40 ? wm : wl) + j*EMB_;
        float a0=0,a1=0,a2=0,a3=0;
        for (int i = 0; i < EMB_; i += 4) {
            a0 += st[i]*w[i];   a1 += st[i+1]*w[i+1];
            a2 += st[i+2]*w[i+2]; a3 += st[i+3]*w[i+3];
        }
        sv[tid] = (a0+a1)+(a2+a3) + (tid < 40 ? bm[j] : bl[j]);
    }
    __syncthreads();
    {
        int which = tid >> 6;
        int e = tid & 63, du = e >> 3, dv = e & 7;
        const float* S = sv + which*40;
        float acc = 0.f;
        #pragma unroll
        for (int p = 0; p < 8; p++)
            #pragma unroll
            for (int q = 0; q < 5; q++) {
                float wq = (q == 0 || q == 4) ? 1.f : 2.f;
                acc += wq * S[p*5 + q] * c_c8[(p*du + q*dv) & 7];
            }
        kk[which][e] = acc * (1.f/64.f);
    }
    __syncthreads();
    for (int idx = tid; idx < 8192; idx += 128) {
        int which = idx >> 12, r = idx & 4095;
        int f = r >> 6, e = r & 63;
        int du = ((e >> 3) - (f >> 3)) & 7;
        int dv = ((e & 7) - (f & 7)) & 7;
        float val = kk[which][du*8 + dv];
        if (which == 0) g_kc1[b*4096 + r] = val;
        else            g_kc2[b*4096 + r] = val;
    }
}

// ---------------- GroupNorm stats ----------------
__global__ __launch_bounds__(256) void k_stats(const float* __restrict__ x, float* __restrict__ st)
{
    int bg = blockIdx.x, tid = threadIdx.x;
    const float* p = x + (size_t)bg * 24576;
    float s = 0.f, s2 = 0.f;
    for (int i = tid; i < 24576; i += 256) { float v = p[i]; s += v; s2 += v*v; }
    __shared__ float rs[8], rq[8];
    for (int o = 16; o; o >>= 1) {
        s  += __shfl_down_sync(0xffffffffu, s,  o);
        s2 += __shfl_down_sync(0xffffffffu, s2, o);
    }
    if ((tid & 31) == 0) { rs[tid>>5] = s; rq[tid>>5] = s2; }
    __syncthreads();
    if (tid == 0) {
        float S = 0.f, Q = 0.f;
        for (int i = 0; i < 8; i++) { S += rs[i]; Q += rq[i]; }
        float mu = S / 24576.f;
        float var = Q / 24576.f - mu*mu;
        st[bg*2]   = mu;
        st[bg*2+1] = rsqrtf(var + 1e-5f);
    }
}

// ---------------- GN apply + AdaFM circulant GEMM (unchanged from R12) ----------------
__global__ __launch_bounds__(256) void k_gn_ada(
    const float* __restrict__ x, const float* __restrict__ st,
    const float* __restrict__ gma, const float* __restrict__ bta,
    const float* __restrict__ kcT, float* __restrict__ out)
{
    extern __shared__ float smg[];
    float* Ks  = smg;          // [f][e] 4096
    float* spT = Ks + 4096;    // [f=64][c=192 pad 194]
    int pi = blockIdx.x, b = blockIdx.y;
    int pr = pi >> 3, pc = pi & 7;
    int tid = threadIdx.x;
    const float4* kc4 = (const float4*)(kcT + b*4096);
    #pragma unroll
    for (int i = 0; i < 4; i++) ((float4*)Ks)[tid + i*256] = kc4[tid + i*256];
    for (int i = tid; i < 12288; i += 256) {
        int ch = i >> 6, rc = i & 63;
        int g = ch / 6;
        float mu = st[(b*32+g)*2], rsd = st[(b*32+g)*2 + 1];
        float v = x[(size_t)(b*192 + ch)*4096 + (pr*8 + (rc>>3))*64 + pc*8 + (rc&7)];
        spT[rc*194 + ch] = (v - mu) * rsd * gma[ch] + bta[ch];
    }
    __syncthreads();
    int e0 = (tid & 15) * 4, c0 = (tid >> 4) * 12;
    ull acc2[4][6];
    #pragma unroll
    for (int i = 0; i < 4; i++)
        #pragma unroll
        for (int t = 0; t < 6; t++) acc2[i][t] = 0ULL;
    #pragma unroll 2
    for (int f = 0; f < 64; f++) {
        float4 a4 = *(const float4*)&Ks[f*64 + e0];
        const float* sp = &spT[f*194 + c0];
        ull bv[6];
        #pragma unroll
        for (int t = 0; t < 6; t++) bv[t] = *(const ull*)&sp[t*2];
        float as[4] = {a4.x, a4.y, a4.z, a4.w};
        #pragma unroll
        for (int i = 0; i < 4; i++) {
            ull da = dup2(as[i]);
            #pragma unroll
            for (int t = 0; t < 6; t++) fma2(acc2[i][t], da, bv[t]);
        }
    }
    #pragma unroll
    for (int i = 0; i < 4; i++) {
        int e = e0 + i;
        int row = pr*8 + (e >> 3), col = pc*8 + (e & 7);
        float* op = &out[((size_t)(b*64 + row)*64 + col)*192 + c0];
        #pragma unroll
        for (int q = 0; q < 3; q++) {
            float l0,h0,l1,h1;
            unpk(acc2[i][2*q], l0, h0);
            unpk(acc2[i][2*q+1], l1, h1);
            *(float4*)&op[q*4] = make_float4(l0, h0, l1, h1);
        }
    }
}

// ---------------- fused window attention (unchanged from R12, 256 thr) ----------------
__global__ __launch_bounds__(256) void k_attn(
    const float* __restrict__ h, const float* __restrict__ xin,
    const float* __restrict__ qkvT, const float* __restrict__ qkv_b,
    const float* __restrict__ rpb, const float* __restrict__ pT,
    const float* __restrict__ proj_b, float* __restrict__ xa)
{
    extern __shared__ float sm[];
    float* xwT  = sm;              // [192][64]   12288
    float* wb   = xwT + 12288;     // [192][96]   18432
    float* qT   = wb + 18432;      // [32][64]    2048
    float* kT   = qT + 2048;       // [32][64]    2048
    float* vS   = kT + 2048;       // [64][32]    2048
    float* A    = vS + 2048;       // [64][65]    4160
    float* outT = A + 4160;        // [192][64]   12288
    float* rb   = outT + 12288;    // 240
    __shared__ int lab[64];

    int tid = threadIdx.x;
    int b = blockIdx.x >> 6, win = blockIdx.x & 63;
    int wr = win >> 3, wc = win & 7;

    #pragma unroll
    for (int it = 0; it < 3; it++) {
        int idx = it*256 + tid;
        int n4 = idx & 15, k4 = idx >> 4;
        float4 r4[4];
        #pragma unroll
        for (int r = 0; r < 4; r++) {
            int n = n4*4 + r;
            int rr = (wr*8 + (n >> 3) + 4) & 63;
            int cc = (wc*8 + (n & 7) + 4) & 63;
            r4[r] = *(const float4*)&h[((size_t)((b*64 + rr)*64 + cc))*192 + k4*4];
        }
        #pragma unroll
        for (int j = 0; j < 4; j++) {
            float4 o;
            o.x = ((const float*)&r4[0])[j];
            o.y = ((const float*)&r4[1])[j];
            o.z = ((const float*)&r4[2])[j];
            o.w = ((const float*)&r4[3])[j];
            *(float4*)&xwT[(k4*4 + j)*64 + n4*4] = o;
        }
    }
    if (tid < 64) {
        int r = wr*8 + (tid >> 3), c = wc*8 + (tid & 7);
        int ra = (r < 56) ? 0 : (r < 60 ? 1 : 2);
        int ca = (c < 56) ? 0 : (c < 60 ? 1 : 2);
        lab[tid] = ra*3 + ca;
    }

    int mt = tid & 15, nt = tid >> 4;
    int m0 = mt * 4;

    for (int head = 0; head < 6; head++) {
        __syncthreads();
        {
            const float4* srcw = (const float4*)(qkvT + head*18432);
            float4* dstw = (float4*)wb;
            #pragma unroll
            for (int i = 0; i < 18; i++) dstw[tid + i*256] = srcw[tid + i*256];
        }
        if (tid < 225) rb[tid] = rpb[tid*6 + head];
        __syncthreads();

        // ---- QKV: 64x96, K=192, tile 4x6 (3 packed pairs) ----
        {
            int j0 = nt * 6;
            ull acc2[4][3];
            #pragma unroll
            for (int i = 0; i < 4; i++)
                #pragma unroll
                for (int j = 0; j < 3; j++) acc2[i][j] = 0ULL;
            #pragma unroll 2
            for (int k2 = 0; k2 < 192; k2++) {
                float4 xv4 = *(const float4*)&xwT[k2*64 + m0];
                const float* wrow = &wb[k2*96 + j0];
                ull w0 = *(const ull*)&wrow[0];
                ull w1 = *(const ull*)&wrow[2];
                ull w2 = *(const ull*)&wrow[4];
                float xs[4] = {xv4.x, xv4.y, xv4.z, xv4.w};
                #pragma unroll
                for (int i = 0; i < 4; i++) {
                    ull xd = dup2(xs[i]);
                    fma2(acc2[i][0], xd, w0);
                    fma2(acc2[i][1], xd, w1);
                    fma2(acc2[i][2], xd, w2);
                }
            }
            #pragma unroll
            for (int jp = 0; jp < 3; jp++) {
                #pragma unroll
                for (int i = 0; i < 4; i++) {
                    float lo, hi;
                    unpk(acc2[i][jp], lo, hi);
                    float vals[2] = {lo, hi};
                    #pragma unroll
                    for (int s = 0; s < 2; s++) {
                        int j = j0 + jp*2 + s, kind = j >> 5, d = j & 31;
                        float val = vals[s] + qkv_b[kind*192 + head*32 + d];
                        if (kind == 0)      qT[d*64 + m0 + i] = val * SCALE_;
                        else if (kind == 1) kT[d*64 + m0 + i] = val;
                        else                vS[(m0+i)*32 + d] = val;
                    }
                }
            }
        }
        __syncthreads();

        // ---- logits: 64x64, K=32, tile 4x4 (2 packed pairs) ----
        {
            int n0 = mt * 4, mm0 = nt * 4;
            ull acc2[4][2];
            #pragma unroll
            for (int i = 0; i < 4; i++) { acc2[i][0] = 0ULL; acc2[i][1] = 0ULL; }
            #pragma unroll 4
            for (int d = 0; d < 32; d++) {
                float4 qv = *(const float4*)&qT[d*64 + n0];
                float4 kv = *(const float4*)&kT[d*64 + mm0];
                ull k01 = ((const ull*)&kv)[0];
                ull k23 = ((const ull*)&kv)[1];
                float qs[4] = {qv.x, qv.y, qv.z, qv.w};
                #pragma unroll
                for (int i = 0; i < 4; i++) {
                    ull qd = dup2(qs[i]);
                    fma2(acc2[i][0], qd, k01);
                    fma2(acc2[i][1], qd, k23);
                }
            }
            #pragma unroll
            for (int i = 0; i < 4; i++) {
                float v01[2], v23[2];
                unpk(acc2[i][0], v01[0], v01[1]);
                unpk(acc2[i][1], v23[0], v23[1]);
                float vals[4] = {v01[0], v01[1], v23[0], v23[1]};
                int n = n0 + i;
                #pragma unroll
                for (int j = 0; j < 4; j++) {
                    int m = mm0 + j;
                    int di = (n >> 3) - (m >> 3) + 7;
                    int dj = (n & 7) - (m & 7) + 7;
                    float v = vals[j] + rb[di*15 + dj];
                    if (lab[n] != lab[m]) v -= 100.f;
                    A[n*65 + m] = v;
                }
            }
        }
        __syncthreads();

        // ---- softmax: 4 lanes per row ----
        {
            int r = tid >> 2, q = tid & 3;
            float* ar = A + r*65;
            int mlo = q*16;
            float mx = ar[mlo];
            #pragma unroll 5
            for (int m2 = 1; m2 < 16; m2++) mx = fmaxf(mx, ar[mlo + m2]);
            mx = fmaxf(mx, __shfl_xor_sync(0xffffffffu, mx, 1, 4));
            mx = fmaxf(mx, __shfl_xor_sync(0xffffffffu, mx, 2, 4));
            float s = 0.f;
            #pragma unroll 4
            for (int m2 = 0; m2 < 16; m2++) {
                float ex = expf(ar[mlo + m2] - mx);
                ar[mlo + m2] = ex;
                s += ex;
            }
            s += __shfl_xor_sync(0xffffffffu, s, 1, 4);
            s += __shfl_xor_sync(0xffffffffu, s, 2, 4);
            float inv = 1.f / s;
            #pragma unroll 4
            for (int m2 = 0; m2 < 16; m2++) ar[mlo + m2] *= inv;
        }
        __syncthreads();

        // ---- AV: 64x32, K=64, tile 4x2 (1 packed pair) ----
        {
            int n0 = mt * 4, d0 = nt * 2;
            ull acc2[4] = {0ULL, 0ULL, 0ULL, 0ULL};
            #pragma unroll 4
            for (int m2 = 0; m2 < 64; m2++) {
                ull vv = *(const ull*)&vS[m2*32 + d0];
                #pragma unroll
                for (int i = 0; i < 4; i++)
                    fma2(acc2[i], dup2(A[(n0+i)*65 + m2]), vv);
            }
            #pragma unroll
            for (int i = 0; i < 4; i++) {
                float lo, hi;
                unpk(acc2[i], lo, hi);
                outT[(head*32 + d0    )*64 + n0 + i] = lo;
                outT[(head*32 + d0 + 1)*64 + n0 + i] = hi;
            }
        }
    }

    // ---- proj + residual + reverse roll (2 chunks of 96 cols) ----
    for (int cch = 0; cch < 2; cch++) {
        __syncthreads();
        {
            const float* srcp = pT + cch*96;
            for (int i4 = tid; i4 < 4608; i4 += 256) {
                int i = i4 / 24, j4 = i4 % 24;
                *(float4*)&wb[i*96 + j4*4] = *(const float4*)&srcp[i*192 + j4*4];
            }
        }
        __syncthreads();
        int j0 = nt * 6;
        ull acc2[4][3];
        #pragma unroll
        for (int i = 0; i < 4; i++)
            #pragma unroll
            for (int j = 0; j < 3; j++) acc2[i][j] = 0ULL;
        #pragma unroll 2
        for (int k2 = 0; k2 < 192; k2++) {
            float4 xv4 = *(const float4*)&outT[k2*64 + m0];
            const float* wrow = &wb[k2*96 + j0];
            ull w0 = *(const ull*)&wrow[0];
            ull w1 = *(const ull*)&wrow[2];
            ull w2 = *(const ull*)&wrow[4];
            float xs[4] = {xv4.x, xv4.y, xv4.z, xv4.w};
            #pragma unroll
            for (int i = 0; i < 4; i++) {
                ull xd = dup2(xs[i]);
                fma2(acc2[i][0], xd, w0);
                fma2(acc2[i][1], xd, w1);
                fma2(acc2[i][2], xd, w2);
            }
        }
        #pragma unroll
        for (int jp = 0; jp < 3; jp++) {
            #pragma unroll
            for (int i = 0; i < 4; i++) {
                float lo, hi;
                unpk(acc2[i][jp], lo, hi);
                float vals[2] = {lo, hi};
                int n = m0 + i;
                int fr = (wr*8 + (n >> 3) + 4) & 63;
                int fc = (wc*8 + (n & 7) + 4) & 63;
                #pragma unroll
                for (int s = 0; s < 2; s++) {
                    int co = cch*96 + j0 + jp*2 + s;
                    size_t gi = ((size_t)((b*192 + co)*64 + fr))*64 + fc;
                    xa[gi] = xin[gi] + vals[s] + proj_b[co];
                }
            }
        }
    }
}

// ---------------- fused MLP: 48-wide chunks, 96KB smem, 2 CTAs/SM ----------------
__global__ __launch_bounds__(256, 2) void k_mlp(
    const float* __restrict__ h2, const float* __restrict__ xa,
    const float* __restrict__ f1T, const float* __restrict__ fc1_b,
    const float* __restrict__ f2T, const float* __restrict__ fc2_b,
    float* __restrict__ out)
{
    extern __shared__ float sm[];
    float* xtT  = sm;            // [192][64]  12288 (k-major)
    float* hidT = xtT + 12288;   // [48][64]   3072
    float* wb   = hidT + 3072;   // 9216 (f1: [192][48] | f2: [48][192])
    int tid = threadIdx.x;
    int b = blockIdx.x >> 6, hh = blockIdx.x & 63;
    const float* src = h2 + ((size_t)(b*64 + hh))*64*192;

    // stage tokens k-major via 4x4 register transpose
    #pragma unroll
    for (int it = 0; it < 3; it++) {
        int idx = it*256 + tid;
        int n4 = idx & 15, k4 = idx >> 4;
        float4 r4[4];
        #pragma unroll
        for (int r = 0; r < 4; r++)
            r4[r] = *(const float4*)&src[(n4*4 + r)*192 + k4*4];
        #pragma unroll
        for (int j = 0; j < 4; j++) {
            float4 o;
            o.x = ((const float*)&r4[0])[j];
            o.y = ((const float*)&r4[1])[j];
            o.z = ((const float*)&r4[2])[j];
            o.w = ((const float*)&r4[3])[j];
            *(float4*)&xtT[(k4*4 + j)*64 + n4*4] = o;
        }
    }

    int mt = tid & 15, ct = tid >> 4;
    int m0 = mt * 4;
    int co0 = ct * 12;
    ull oacc[4][6];
    #pragma unroll
    for (int i = 0; i < 4; i++)
        #pragma unroll
        for (int j = 0; j < 6; j++) oacc[i][j] = 0ULL;

    for (int chunk = 0; chunk < 16; chunk++) {
        __syncthreads();
        // stage f1 chunk [192][48]
        #pragma unroll
        for (int i = 0; i < 9; i++) {
            int i4 = tid + i*256;       // 0..2303
            int k = i4 / 12, j4 = i4 % 12;
            *(float4*)&wb[k*48 + j4*4] = *(const float4*)&f1T[k*768 + chunk*48 + j4*4];
        }
        __syncthreads();
        // ---- GEMM1: 64x48, K=192, tile 4m(m-packed) x 3j -> gelu -> hidT ----
        {
            int j0 = ct * 3;
            ull acc[3][2];
            #pragma unroll
            for (int j = 0; j < 3; j++) { acc[j][0] = 0ULL; acc[j][1] = 0ULL; }
            #pragma unroll 2
            for (int k2 = 0; k2 < 192; k2++) {
                float4 xv = *(const float4*)&xtT[k2*64 + m0];
                ull xp0 = ((const ull*)&xv)[0];
                ull xp1 = ((const ull*)&xv)[1];
                const float* wr2 = &wb[k2*48 + j0];
                #pragma unroll
                for (int j = 0; j < 3; j++) {
                    ull dw = dup2(wr2[j]);
                    fma2(acc[j][0], dw, xp0);
                    fma2(acc[j][1], dw, xp1);
                }
            }
            #pragma unroll
            for (int j = 0; j < 3; j++) {
                float bias = fc1_b[chunk*48 + j0 + j];
                float a0,a1,a2,a3;
                unpk(acc[j][0], a0, a1);
                unpk(acc[j][1], a2, a3);
                a0 += bias; a1 += bias; a2 += bias; a3 += bias;
                a0 = 0.5f * a0 * (1.f + erff(a0 * 0.70710678118654752f));
                a1 = 0.5f * a1 * (1.f + erff(a1 * 0.70710678118654752f));
                a2 = 0.5f * a2 * (1.f + erff(a2 * 0.70710678118654752f));
                a3 = 0.5f * a3 * (1.f + erff(a3 * 0.70710678118654752f));
                *(float4*)&hidT[(j0+j)*64 + m0] = make_float4(a0, a1, a2, a3);
            }
        }
        __syncthreads();
        // stage f2 chunk [48][192] (contiguous)
        {
            const float4* s4 = (const float4*)(f2T + chunk*9216);
            float4* d4 = (float4*)wb;
            #pragma unroll
            for (int i = 0; i < 9; i++) d4[tid + i*256] = s4[tid + i*256];
        }
        __syncthreads();
        // ---- GEMM2: 64x192, K=48, tile 4m x 12co (co-packed), accumulate ----
        #pragma unroll 2
        for (int jL = 0; jL < 48; jL++) {
            float4 xv4 = *(const float4*)&hidT[jL*64 + m0];
            const float* wrow = &wb[jL*192 + co0];
            float4 wA = *(const float4*)&wrow[0];
            float4 wBv = *(const float4*)&wrow[4];
            float4 wC = *(const float4*)&wrow[8];
            ull wp[6] = {((const ull*)&wA)[0], ((const ull*)&wA)[1],
                         ((const ull*)&wBv)[0], ((const ull*)&wBv)[1],
                         ((const ull*)&wC)[0], ((const ull*)&wC)[1]};
            float xs[4] = {xv4.x, xv4.y, xv4.z, xv4.w};
            #pragma unroll
            for (int i = 0; i < 4; i++) {
                ull xd = dup2(xs[i]);
                #pragma unroll
                for (int j = 0; j < 6; j++) fma2(oacc[i][j], xd, wp[j]);
            }
        }
    }
    // epilogue: bias + residual, BCHW
    #pragma unroll
    for (int j = 0; j < 6; j++) {
        #pragma unroll
        for (int i = 0; i < 4; i++) {
            float lo, hi;
            unpk(oacc[i][j], lo, hi);
            float vals[2] = {lo, hi};
            #pragma unroll
            for (int s = 0; s < 2; s++) {
                int co = co0 + j*2 + s;
                size_t gi = ((size_t)((b*192 + co)*64 + hh))*64 + m0 + i;
                out[gi] = xa[gi] + vals[s] + fc2_b[co];
            }
        }
    }
}

// ---------------- launcher ----------------
extern "C" void kernel_launch(void* const* d_in, const int* in_sizes, int n_in,
                              void* d_out, int out_size)
{
    const float* x        = (const float*)d_in[0];
    const float* t        = (const float*)d_in[1];
    const float* n1_w     = (const float*)d_in[2];
    const float* n1_b     = (const float*)d_in[3];
    const float* qkv_w    = (const float*)d_in[4];
    const float* qkv_b    = (const float*)d_in[5];
    const float* rpb      = (const float*)d_in[6];
    const float* proj_w   = (const float*)d_in[7];
    const float* proj_b   = (const float*)d_in[8];
    const float* n2_w     = (const float*)d_in[9];
    const float* n2_b     = (const float*)d_in[10];
    const float* fc1_w    = (const float*)d_in[11];
    const float* fc1_b    = (const float*)d_in[12];
    const float* fc2_w    = (const float*)d_in[13];
    const float* fc2_b    = (const float*)d_in[14];
    const float* ada_msa_w = (const float*)d_in[15];
    const float* ada_msa_b = (const float*)d_in[16];
    const float* ada_mlp_w = (const float*)d_in[17];
    const float* ada_mlp_b = (const float*)d_in[18];
    float* out = (float*)d_out;

    float *p_h, *p_xa, *p_h2, *p_kc1, *p_kc2, *p_st1, *p_st2;
    float *p_qkvT, *p_pT, *p_f1T, *p_f2T;
    cudaGetSymbolAddress((void**)&p_h,    g_h);
    cudaGetSymbolAddress((void**)&p_xa,   g_xa);
    cudaGetSymbolAddress((void**)&p_h2,   g_h2);
    cudaGetSymbolAddress((void**)&p_kc1,  g_kc1);
    cudaGetSymbolAddress((void**)&p_kc2,  g_kc2);
    cudaGetSymbolAddress((void**)&p_st1,  g_st1);
    cudaGetSymbolAddress((void**)&p_st2,  g_st2);
    cudaGetSymbolAddress((void**)&p_qkvT, g_qkvT);
    cudaGetSymbolAddress((void**)&p_pT,   g_pT);
    cudaGetSymbolAddress((void**)&p_f1T,  g_f1T);
    cudaGetSymbolAddress((void**)&p_f2T,  g_f2T);

    cudaFuncSetAttribute(k_gn_ada, cudaFuncAttributeMaxDynamicSharedMemorySize, 66048);
    cudaFuncSetAttribute(k_attn, cudaFuncAttributeMaxDynamicSharedMemorySize, 214208);
    cudaFuncSetAttribute(k_mlp,  cudaFuncAttributeMaxDynamicSharedMemorySize, 98304);

    k_prep<<<1728, 256>>>(qkv_w, proj_w, fc1_w, fc2_w);
    k0_ada<<<32, 128>>>(t, ada_msa_w, ada_msa_b, ada_mlp_w, ada_mlp_b);
    k_stats<<<1024, 256>>>(x, p_st1);
    k_gn_ada<<<dim3(64, 32), 256, 66048>>>(x, p_st1, n1_w, n1_b, p_kc1, p_h);
    k_attn<<<2048, 256, 214208>>>(p_h, x, p_qkvT, qkv_b, rpb, p_pT, proj_b, p_xa);
    k_stats<<<1024, 256>>>(p_xa, p_st2);
    k_gn_ada<<<dim3(64, 32), 256, 66048>>>(p_xa, p_st2, n2_w, n2_b, p_kc2, p_h2);
    k_mlp<<<2048, 256, 98304>>>(p_h2, p_xa, p_f1T, fc1_b, p_f2T, fc2_b, out);
}